// round 15
// baseline (speedup 1.0000x reference)
#include <cuda_runtime.h>
#include <math.h>
#include <string.h>

#define B_ 4
#define S_ 4096
#define H_ 2048
#define E_ 16
#define ED_ 512
#define H4 512               // 16-byte units per row
#define NBLK_A 1024
#define ROWS_PER_BLK_A 16
#define BLKS_PER_BATCH 256   // NBLK_A / B_
#define NBLK_B 256

typedef unsigned long long ull;

// ---------------- device scratch ----------------
__device__ float g_part[NBLK_A * H_];     // per-block LN partial sums (8 MB)
__device__ float g_qi[B_ * H_];           // final query_input (affine applied)
__device__ float g_lf[E_ * H_];           // layer_features
__device__ float g_attp[NBLK_B * B_ * E_];
__device__ int g_cb[B_];                  // per-batch arrival counters
__device__ int g_c3;                      // kB arrival counter

__device__ __forceinline__ float warp_sum(float v) {
#pragma unroll
    for (int o = 16; o > 0; o >>= 1) v += __shfl_xor_sync(0xffffffffu, v, o);
    return v;
}
__device__ __forceinline__ ull ffma2(ull a, ull b, ull c) {
    ull d;
    asm("fma.rn.f32x2 %0, %1, %2, %3;" : "=l"(d) : "l"(a), "l"(b), "l"(c));
    return d;
}
__device__ __forceinline__ ull add2(ull a, ull b) {
    ull d;
    asm("add.rn.f32x2 %0, %1, %2;" : "=l"(d) : "l"(a), "l"(b));
    return d;
}
__device__ __forceinline__ float pairsum(ull v) {
    float2 f; memcpy(&f, &v, 8);
    return f.x + f.y;
}
__device__ __forceinline__ ull pack2(float f) {
    float2 t = make_float2(f, f);
    ull r; memcpy(&r, &t, 8);
    return r;
}

// ---------------- Kernel A: LN + mean-over-S; last block per batch builds qi --
__global__ void __launch_bounds__(256, 4) kA(const float* __restrict__ hid,
                                             const float* __restrict__ le,
                                             const float* __restrict__ ce,
                                             const float* __restrict__ gamma,
                                             const float* __restrict__ beta,
                                             const int* __restrict__ curp) {
    __shared__ float2 s_ms[2][8];           // [parity][warp] (sum, sumsq)
    __shared__ ulonglong2 s_acc[4][128];    // rg=1 accumulator staging (8 KB)
    __shared__ float s_mr[4];               // rg=1 mean-correction scalars
    __shared__ int s_red;
    const int tid = threadIdx.x, warp = tid >> 5, lane = tid & 31;
    const int blk = blockIdx.x;
    const int qt = warp & 3, rg = warp >> 2;
    const size_t row0 = (size_t)blk * ROWS_PER_BLK_A;
    const int colbase = qt * 128 + lane;

    const ulonglong2* base = reinterpret_cast<const ulonglong2*>(hid);
    const ulonglong2* p = base + (row0 + rg) * H4 + colbase;

    ulonglong2 v[4];
    ull acc[8];
    float mr = 0.f;                          // sum of mu*rr over this group's rows
#pragma unroll
    for (int i = 0; i < 8; i++) acc[i] = 0ull;
#pragma unroll
    for (int i = 0; i < 4; i++) v[i] = p[i * 32];

    for (int it = 0; it < 8; it++) {
        const ulonglong2* pn = p + ((it < 7) ? 2 * H4 : 0);
        ulonglong2 n0 = pn[0], n1 = pn[32], n2 = pn[64], n3 = pn[96];

        ull sp = 0ull, sq = 0ull;
#pragma unroll
        for (int i = 0; i < 4; i++) {
            sp = add2(sp, v[i].x); sp = add2(sp, v[i].y);
            sq = ffma2(v[i].x, v[i].x, sq);
            sq = ffma2(v[i].y, v[i].y, sq);
        }
        float s = warp_sum(pairsum(sp));
        float s2 = warp_sum(pairsum(sq));
        if (lane == 0) s_ms[it & 1][warp] = make_float2(s, s2);
        __syncthreads();
        const float4* sm = reinterpret_cast<const float4*>(&s_ms[it & 1][rg * 4]);
        float4 p0 = sm[0], p1 = sm[1];
        const float S  = p0.x + p0.z + p1.x + p1.z;
        const float S2 = p0.y + p0.w + p1.y + p1.w;
        const float mu = S * (1.f / H_);
        const float rr = rsqrtf(S2 * (1.f / H_) - mu * mu + 1e-5f);
        const ull rr2 = pack2(rr);
        mr = fmaf(mu, rr, mr);
#pragma unroll
        for (int i = 0; i < 4; i++) {
            acc[2 * i]     = ffma2(v[i].x, rr2, acc[2 * i]);
            acc[2 * i + 1] = ffma2(v[i].y, rr2, acc[2 * i + 1]);
        }
        v[0] = n0; v[1] = n1; v[2] = n2; v[3] = n3;
        p = pn;
    }
    if (rg == 1) {
#pragma unroll
        for (int i = 0; i < 4; i++)
            s_acc[qt][i * 32 + lane] = make_ulonglong2(acc[2 * i], acc[2 * i + 1]);
        if (lane == 0) s_mr[qt] = mr;
    }
    __syncthreads();
    if (rg == 0) {
        const ull nmr2 = pack2(-(mr + s_mr[qt]));
        ulonglong2* o2 = reinterpret_cast<ulonglong2*>(g_part) + (size_t)blk * H4;
#pragma unroll
        for (int i = 0; i < 4; i++) {
            ulonglong2 b = s_acc[qt][i * 32 + lane];
            o2[colbase + i * 32] =
                make_ulonglong2(add2(add2(acc[2 * i], b.x), nmr2),
                                add2(add2(acc[2 * i + 1], b.y), nmr2));
        }
    }

    // ---- tail blocks build lf = le + ce (independent of LN) ----
    if (blk >= NBLK_A - 8) {
        const int bbase = (blk - (NBLK_A - 8)) * 1024 + tid;
        const float4* le4 = reinterpret_cast<const float4*>(le);
        const float4* ce4 = reinterpret_cast<const float4*>(ce);
        float4* lf4 = reinterpret_cast<float4*>(g_lf);
#pragma unroll
        for (int i = 0; i < 4; i++) {
            int idx = bbase + i * 256;
            float4 a = le4[idx], c = ce4[idx];
            lf4[idx] = make_float4(a.x + c.x, a.y + c.y, a.z + c.z, a.w + c.w);
        }
    }

    // ---- per-batch counter; LAST block of each batch reduces -> g_qi ----
    __threadfence();
    __syncthreads();
    const int batch = blk >> 8;
    if (tid == 0) s_red = (atomicAdd(&g_cb[batch], 1) == BLKS_PER_BATCH - 1) ? 1 : 0;
    __syncthreads();
    if (!s_red) return;
    __threadfence();

    const float4* gp = reinterpret_cast<const float4*>(g_part)
                     + (size_t)batch * BLKS_PER_BATCH * H4;
    float4 s0 = make_float4(0.f, 0.f, 0.f, 0.f);
    float4 s1 = make_float4(0.f, 0.f, 0.f, 0.f);
#pragma unroll 8
    for (int c = 0; c < BLKS_PER_BATCH; c++) {
        float4 a = gp[(size_t)c * H4 + tid];
        float4 b = gp[(size_t)c * H4 + tid + 256];
        s0.x += a.x; s0.y += a.y; s0.z += a.z; s0.w += a.w;
        s1.x += b.x; s1.y += b.y; s1.z += b.z; s1.w += b.w;
    }
    const int cur = *curp;
    const float4* g4 = reinterpret_cast<const float4*>(gamma);
    const float4* b4 = reinterpret_cast<const float4*>(beta);
    const float4* l4 = reinterpret_cast<const float4*>(le) + cur * H4;
    float4* qi4 = reinterpret_cast<float4*>(g_qi) + batch * H4;
#pragma unroll
    for (int h = 0; h < 2; h++) {
        int c = tid + h * 256;
        float4 sv = h ? s1 : s0;
        float4 gg = g4[c], bb = b4[c], ll = l4[c];
        float4 r;
        r.x = ll.x + gg.x * (sv.x * (1.f / S_)) + bb.x;
        r.y = ll.y + gg.y * (sv.y * (1.f / S_)) + bb.y;
        r.z = ll.z + gg.z * (sv.z * (1.f / S_)) + bb.z;
        r.w = ll.w + gg.w * (sv.w * (1.f / S_)) + bb.w;
        qi4[c] = r;
    }
}

// ---------------- Kernel B: fused q/k GEMV (2 cols/warp) + epilogue ----------
__global__ void __launch_bounds__(128) kB(const float* __restrict__ Wq,
                                          const float* __restrict__ bq,
                                          const float* __restrict__ Wk,
                                          const float* __restrict__ bk,
                                          const float* __restrict__ spatial,
                                          const float* __restrict__ edge,
                                          const int* __restrict__ curp,
                                          const int* __restrict__ avail,
                                          float* __restrict__ out) {
    __shared__ float s_attp[4][B_ * E_];
    __shared__ float s_red[2][B_ * E_];
    __shared__ float s_att[B_ * E_];
    __shared__ float s_w[ED_];
    __shared__ float s_eb[E_];
    __shared__ float s_sb[E_];
    __shared__ int   s_last;

    const int tid = threadIdx.x, warp = tid >> 5, lane = tid & 31;
    const int j0 = blockIdx.x * 8 + warp * 2;

    ull aq0[B_], aq1[B_], ak0[E_], ak1[E_];
#pragma unroll
    for (int b = 0; b < B_; b++) { aq0[b] = 0ull; aq1[b] = 0ull; }
#pragma unroll
    for (int e = 0; e < E_; e++) { ak0[e] = 0ull; ak1[e] = 0ull; }

    const ulonglong2* wq0 = reinterpret_cast<const ulonglong2*>(Wq) + (size_t)j0 * H4;
    const ulonglong2* wq1 = wq0 + H4;
    const ulonglong2* wk0 = reinterpret_cast<const ulonglong2*>(Wk) + (size_t)j0 * H4;
    const ulonglong2* wk1 = wk0 + H4;
    const ulonglong2* qi = reinterpret_cast<const ulonglong2*>(g_qi);
    const ulonglong2* lf = reinterpret_cast<const ulonglong2*>(g_lf);

#pragma unroll 4
    for (int t = 0; t < 16; t++) {
        const int idx = t * 32 + lane;
        ulonglong2 a0 = wq0[idx], a1 = wq1[idx];
        ulonglong2 c0 = wk0[idx], c1 = wk1[idx];
#pragma unroll
        for (int b = 0; b < B_; b++) {
            ulonglong2 x = qi[b * H4 + idx];
            aq0[b] = ffma2(a0.x, x.x, aq0[b]); aq0[b] = ffma2(a0.y, x.y, aq0[b]);
            aq1[b] = ffma2(a1.x, x.x, aq1[b]); aq1[b] = ffma2(a1.y, x.y, aq1[b]);
        }
#pragma unroll
        for (int e = 0; e < E_; e++) {
            ulonglong2 x = lf[e * H4 + idx];
            ak0[e] = ffma2(c0.x, x.x, ak0[e]); ak0[e] = ffma2(c0.y, x.y, ak0[e]);
            ak1[e] = ffma2(c1.x, x.x, ak1[e]); ak1[e] = ffma2(c1.y, x.y, ak1[e]);
        }
    }
    float q0[B_], q1[B_], k0[E_], k1[E_];
    const float bq0 = bq[j0], bq1 = bq[j0 + 1];
    const float bk0 = bk[j0], bk1 = bk[j0 + 1];
#pragma unroll
    for (int b = 0; b < B_; b++) {
        q0[b] = warp_sum(pairsum(aq0[b])) + bq0;
        q1[b] = warp_sum(pairsum(aq1[b])) + bq1;
    }
#pragma unroll
    for (int e = 0; e < E_; e++) {
        k0[e] = warp_sum(pairsum(ak0[e])) + bk0;
        k1[e] = warp_sum(pairsum(ak1[e])) + bk1;
    }
    if (lane == 0) {
        const float inv_sqrt_h = rsqrtf((float)H_);
#pragma unroll
        for (int b = 0; b < B_; b++)
#pragma unroll
            for (int e = 0; e < E_; e++)
                s_attp[warp][b * E_ + e] = (q0[b] * k0[e] + q1[b] * k1[e]) * inv_sqrt_h;
    }
    __syncthreads();
    if (tid < B_ * E_) {
        float s = s_attp[0][tid] + s_attp[1][tid] + s_attp[2][tid] + s_attp[3][tid];
        g_attp[blockIdx.x * (B_ * E_) + tid] = s;
    }
    __threadfence();
    __syncthreads();
    if (tid == 0) {
        int old = atomicAdd(&g_c3, 1);
        s_last = (old == NBLK_B - 1) ? 1 : 0;
    }
    __syncthreads();
    if (!s_last) return;

    // ================= epilogue (last block only, 128 threads) =================
    const int cur = *curp;
    {
        int o = tid & 63, qc = tid >> 6;   // 2 chunks of 128 blocks
        float s = 0.f;
#pragma unroll 8
        for (int c = 0; c < 128; c++) s += g_attp[(qc * 128 + c) * (B_ * E_) + o];
        s_red[qc][o] = s;
    }
    for (int h = tid; h < ED_; h += 128) {
        float a = 0.f;
#pragma unroll
        for (int i = 0; i < E_; i++) {
            int d = abs(i - cur);
            float rm = (float)avail[i] * ((i != cur) ? 1.f : 0.f) * (1.f / (float)max(d, 1));
            a += rm * edge[i * ED_ + h];
        }
        s_w[h] = a;
    }
    if (tid < E_) s_sb[tid] = spatial[abs(tid - cur)];
    __syncthreads();
    if (tid < B_ * E_) s_att[tid] = s_red[0][tid] + s_red[1][tid];

    for (int jj = 0; jj < 4; jj++) {
        int je = warp * 4 + jj;
        float s = 0.f;
#pragma unroll
        for (int t = 0; t < 16; t++)
            s += s_w[t * 32 + lane] * edge[je * ED_ + t * 32 + lane];
        s = warp_sum(s);
        if (lane == 0) s_eb[je] = s;
    }
    __syncthreads();

    if (warp == 0) {
        float av = (lane < E_) ? (float)avail[lane] : 0.f;
        float num_avail = warp_sum(av);
        float tprob = 1.f / num_avail;
        float logt = logf(tprob);
        float klacc = 0.f;
        int nidx = 0;
        for (int b = 0; b < B_; b++) {
            float sc = -1e30f;
            if (lane < E_) {
                bool ok = (avail[lane] > 0);
                sc = s_att[b * E_ + lane] + s_sb[lane] + s_eb[lane];
                sc = ok ? sc : -1e9f;
            }
            float m = sc;
#pragma unroll
            for (int o = 8; o > 0; o >>= 1) m = fmaxf(m, __shfl_xor_sync(0xffffffffu, m, o, 16));
            float ex = (lane < E_) ? __expf(sc - m) : 0.f;
            float sum = ex;
#pragma unroll
            for (int o = 8; o > 0; o >>= 1) sum += __shfl_xor_sync(0xffffffffu, sum, o, 16);
            float p = (lane < E_) ? (ex / sum) : 0.f;
            if (lane < E_) out[1 + b * E_ + lane] = p;
            float ps = fmaxf(p, 1e-10f);
            if (lane < E_) klacc += tprob * (logt - logf(ps));
            if (b == 0) {
                float pm = (lane < E_) ? p : -1.f;
                float mm = pm;
#pragma unroll
                for (int o = 16; o > 0; o >>= 1) mm = fmaxf(mm, __shfl_xor_sync(0xffffffffu, mm, o));
                unsigned bal = __ballot_sync(0xffffffffu, pm == mm);
                nidx = __ffs(bal) - 1;
            }
        }
        float kl = warp_sum(klacc);
        if (lane == 0) {
            out[0] = (kl / (float)B_) * 0.01f;
            out[1 + B_ * E_] = (float)nidx;
            g_c3 = 0;                     // reset for next graph replay
        }
        if (lane < B_) g_cb[lane] = 0;    // reset per-batch counters
    }
}

// ---------------- launch ----------------
extern "C" void kernel_launch(void* const* d_in, const int* in_sizes, int n_in,
                              void* d_out, int out_size) {
    const float* hid     = (const float*)d_in[0];
    const float* le      = (const float*)d_in[1];
    const float* ce      = (const float*)d_in[2];
    const float* spatial = (const float*)d_in[3];
    const float* edge    = (const float*)d_in[4];
    const float* gamma   = (const float*)d_in[5];
    const float* beta    = (const float*)d_in[6];
    const float* Wq      = (const float*)d_in[7];
    const float* bq      = (const float*)d_in[8];
    const float* Wk      = (const float*)d_in[9];
    const float* bk      = (const float*)d_in[10];
    // d_in[11], d_in[12] (Wv, bv) intentionally unused: v is dead in the reference
    const int*   curp    = (const int*)d_in[13];
    const int*   avail   = (const int*)d_in[14];
    float* out = (float*)d_out;

    kA<<<NBLK_A, 256>>>(hid, le, ce, gamma, beta, curp);
    kB<<<NBLK_B, 128>>>(Wq, bq, Wk, bk, spatial, edge, curp, avail, out);
}

// round 16
// speedup vs baseline: 1.3263x; 1.3263x over previous
#include <cuda_runtime.h>
#include <math.h>
#include <string.h>

#define B_ 4
#define S_ 4096
#define H_ 2048
#define E_ 16
#define ED_ 512
#define H4 512               // 16-byte units per row
#define NBLK_A 1024
#define ROWS_PER_BLK_A 16
#define BLKS_PER_BATCH 256   // NBLK_A / B_
#define NBLK_B 256

typedef unsigned long long ull;

// ---------------- device scratch ----------------
__device__ float g_part[NBLK_A * H_];     // per-block LN partial sums (8 MB)
__device__ float g_qi[B_ * H_];           // final query_input (affine applied)
__device__ float g_lf[E_ * H_];           // layer_features
__device__ float g_attp[NBLK_B * B_ * E_];
__device__ int g_c3;                      // kB arrival counter (zero-init; reset below)

__device__ __forceinline__ float warp_sum(float v) {
#pragma unroll
    for (int o = 16; o > 0; o >>= 1) v += __shfl_xor_sync(0xffffffffu, v, o);
    return v;
}
__device__ __forceinline__ ull ffma2(ull a, ull b, ull c) {
    ull d;
    asm("fma.rn.f32x2 %0, %1, %2, %3;" : "=l"(d) : "l"(a), "l"(b), "l"(c));
    return d;
}
__device__ __forceinline__ ull add2(ull a, ull b) {
    ull d;
    asm("add.rn.f32x2 %0, %1, %2;" : "=l"(d) : "l"(a), "l"(b));
    return d;
}
__device__ __forceinline__ float pairsum(ull v) {
    float2 f; memcpy(&f, &v, 8);
    return f.x + f.y;
}
__device__ __forceinline__ ull pack2(float f) {
    float2 t = make_float2(f, f);
    ull r; memcpy(&r, &t, 8);
    return r;
}

// ---------------- Kernel A: LN + mean-over-S partials (+ lf build in tail) ----
__global__ void __launch_bounds__(256, 4) kA(const float* __restrict__ hid,
                                             const float* __restrict__ le,
                                             const float* __restrict__ ce) {
    __shared__ float2 s_ms[2][8];           // [parity][warp] (sum, sumsq)
    __shared__ ulonglong2 s_acc[4][128];    // rg=1 accumulator staging (8 KB)
    __shared__ float s_mr[4];               // rg=1 mean-correction scalars
    const int tid = threadIdx.x, warp = tid >> 5, lane = tid & 31;
    const int blk = blockIdx.x;
    const int qt = warp & 3, rg = warp >> 2;
    const size_t row0 = (size_t)blk * ROWS_PER_BLK_A;
    const int colbase = qt * 128 + lane;

    const ulonglong2* base = reinterpret_cast<const ulonglong2*>(hid);
    const ulonglong2* p = base + (row0 + rg) * H4 + colbase;

    ulonglong2 v[4];
    ull acc[8];
    float mr = 0.f;                          // sum of mu*rr over this group's rows
#pragma unroll
    for (int i = 0; i < 8; i++) acc[i] = 0ull;
#pragma unroll
    for (int i = 0; i < 4; i++) v[i] = p[i * 32];

    for (int it = 0; it < 8; it++) {
        const ulonglong2* pn = p + ((it < 7) ? 2 * H4 : 0);
        ulonglong2 n0 = pn[0], n1 = pn[32], n2 = pn[64], n3 = pn[96];

        ull sp = 0ull, sq = 0ull;
#pragma unroll
        for (int i = 0; i < 4; i++) {
            sp = add2(sp, v[i].x); sp = add2(sp, v[i].y);
            sq = ffma2(v[i].x, v[i].x, sq);
            sq = ffma2(v[i].y, v[i].y, sq);
        }
        float s = warp_sum(pairsum(sp));
        float s2 = warp_sum(pairsum(sq));
        if (lane == 0) s_ms[it & 1][warp] = make_float2(s, s2);
        __syncthreads();
        const float4* sm = reinterpret_cast<const float4*>(&s_ms[it & 1][rg * 4]);
        float4 p0 = sm[0], p1 = sm[1];
        const float S  = p0.x + p0.z + p1.x + p1.z;
        const float S2 = p0.y + p0.w + p1.y + p1.w;
        const float mu = S * (1.f / H_);
        const float rr = rsqrtf(S2 * (1.f / H_) - mu * mu + 1e-5f);
        const ull rr2 = pack2(rr);
        mr = fmaf(mu, rr, mr);
#pragma unroll
        for (int i = 0; i < 4; i++) {
            acc[2 * i]     = ffma2(v[i].x, rr2, acc[2 * i]);
            acc[2 * i + 1] = ffma2(v[i].y, rr2, acc[2 * i + 1]);
        }
        v[0] = n0; v[1] = n1; v[2] = n2; v[3] = n3;
        p = pn;
    }
    if (rg == 1) {
#pragma unroll
        for (int i = 0; i < 4; i++)
            s_acc[qt][i * 32 + lane] = make_ulonglong2(acc[2 * i], acc[2 * i + 1]);
        if (lane == 0) s_mr[qt] = mr;
    }
    __syncthreads();
    if (rg == 0) {
        const ull nmr2 = pack2(-(mr + s_mr[qt]));
        ulonglong2* o2 = reinterpret_cast<ulonglong2*>(g_part) + (size_t)blk * H4;
#pragma unroll
        for (int i = 0; i < 4; i++) {
            ulonglong2 b = s_acc[qt][i * 32 + lane];
            o2[colbase + i * 32] =
                make_ulonglong2(add2(add2(acc[2 * i], b.x), nmr2),
                                add2(add2(acc[2 * i + 1], b.y), nmr2));
        }
    }
    // ---- tail blocks build lf = le + ce (independent of LN) ----
    if (blk >= NBLK_A - 8) {
        const int bbase = (blk - (NBLK_A - 8)) * 1024 + tid;
        const float4* le4 = reinterpret_cast<const float4*>(le);
        const float4* ce4 = reinterpret_cast<const float4*>(ce);
        float4* lf4 = reinterpret_cast<float4*>(g_lf);
#pragma unroll
        for (int i = 0; i < 4; i++) {
            int idx = bbase + i * 256;
            float4 a = le4[idx], c = ce4[idx];
            lf4[idx] = make_float4(a.x + c.x, a.y + c.y, a.z + c.z, a.w + c.w);
        }
    }
}

// ---------------- Kernel B0: parallel qi reduce (64 blocks) ------------------
__global__ void __launch_bounds__(256) kB0(const float* __restrict__ le,
                                           const float* __restrict__ gamma,
                                           const float* __restrict__ beta,
                                           const int* __restrict__ curp) {
    __shared__ float4 s_q[8][32];
    const int blk = blockIdx.x;
    const int b = blk >> 4, chunk = blk & 15;
    const int lane = threadIdx.x & 31, csub = threadIdx.x >> 5;
    const int h4i = chunk * 32 + lane;
    const float4* gp = reinterpret_cast<const float4*>(g_part);
    size_t basep = ((size_t)(b * BLKS_PER_BATCH + csub * 32)) * H4 + h4i;
    float4 s = make_float4(0.f, 0.f, 0.f, 0.f);
#pragma unroll
    for (int c = 0; c < 32; c++) {
        float4 t = gp[basep + (size_t)c * H4];
        s.x += t.x; s.y += t.y; s.z += t.z; s.w += t.w;
    }
    s_q[csub][lane] = s;
    __syncthreads();
    if (threadIdx.x < 32) {
        float4 t = s_q[0][lane];
#pragma unroll
        for (int q = 1; q < 8; q++) {
            float4 u = s_q[q][lane];
            t.x += u.x; t.y += u.y; t.z += u.z; t.w += u.w;
        }
        const int cur = *curp;
        float4 g4 = reinterpret_cast<const float4*>(gamma)[h4i];
        float4 b4 = reinterpret_cast<const float4*>(beta)[h4i];
        float4 l4 = reinterpret_cast<const float4*>(le)[cur * H4 + h4i];
        float4 r;
        r.x = l4.x + g4.x * (t.x * (1.f / S_)) + b4.x;
        r.y = l4.y + g4.y * (t.y * (1.f / S_)) + b4.y;
        r.z = l4.z + g4.z * (t.z * (1.f / S_)) + b4.z;
        r.w = l4.w + g4.w * (t.w * (1.f / S_)) + b4.w;
        reinterpret_cast<float4*>(g_qi)[b * H4 + h4i] = r;
    }
}

// ---------------- Kernel B: q/k GEMV, experts split across warp pairs --------
// 256 blocks x 256 threads. Warp pair owns 2 columns; even warp does q + experts
// 0..7, odd warp experts 8..15. Accumulators: 24 ull = 48 regs -> no spills.
__global__ void __launch_bounds__(256, 2) kB(const float* __restrict__ Wq,
                                             const float* __restrict__ bq,
                                             const float* __restrict__ Wk,
                                             const float* __restrict__ bk,
                                             const float* __restrict__ spatial,
                                             const float* __restrict__ edge,
                                             const int* __restrict__ curp,
                                             const int* __restrict__ avail,
                                             float* __restrict__ out) {
    __shared__ float s_attp[8][B_ * 8];
    __shared__ float s_qv[4][2][B_];
    __shared__ float s_red[4][B_ * E_];
    __shared__ float s_att[B_ * E_];
    __shared__ float s_w[ED_];
    __shared__ float s_eb[E_];
    __shared__ float s_sb[E_];
    __shared__ int   s_last;

    const int tid = threadIdx.x, warp = tid >> 5, lane = tid & 31;
    const int half = warp & 1, pair = warp >> 1;
    const int j0 = blockIdx.x * 8 + pair * 2;
    const int ebase = half * 8;

    ull aq0[B_], aq1[B_], ak0[8], ak1[8];
#pragma unroll
    for (int b = 0; b < B_; b++) { aq0[b] = 0ull; aq1[b] = 0ull; }
#pragma unroll
    for (int e = 0; e < 8; e++) { ak0[e] = 0ull; ak1[e] = 0ull; }

    const ulonglong2* wq0 = reinterpret_cast<const ulonglong2*>(Wq) + (size_t)j0 * H4;
    const ulonglong2* wq1 = wq0 + H4;
    const ulonglong2* wk0 = reinterpret_cast<const ulonglong2*>(Wk) + (size_t)j0 * H4;
    const ulonglong2* wk1 = wk0 + H4;
    const ulonglong2* qi = reinterpret_cast<const ulonglong2*>(g_qi);
    const ulonglong2* lf = reinterpret_cast<const ulonglong2*>(g_lf)
                         + (size_t)ebase * H4;

#pragma unroll 2
    for (int t = 0; t < 16; t++) {
        const int idx = t * 32 + lane;
        ulonglong2 c0 = wk0[idx], c1 = wk1[idx];
        if (half == 0) {
            ulonglong2 a0 = wq0[idx], a1 = wq1[idx];
#pragma unroll
            for (int b = 0; b < B_; b++) {
                ulonglong2 x = qi[b * H4 + idx];
                aq0[b] = ffma2(a0.x, x.x, aq0[b]); aq0[b] = ffma2(a0.y, x.y, aq0[b]);
                aq1[b] = ffma2(a1.x, x.x, aq1[b]); aq1[b] = ffma2(a1.y, x.y, aq1[b]);
            }
        }
#pragma unroll
        for (int e = 0; e < 8; e++) {
            ulonglong2 x = lf[e * H4 + idx];
            ak0[e] = ffma2(c0.x, x.x, ak0[e]); ak0[e] = ffma2(c0.y, x.y, ak0[e]);
            ak1[e] = ffma2(c1.x, x.x, ak1[e]); ak1[e] = ffma2(c1.y, x.y, ak1[e]);
        }
    }
    // reductions + biases
    float k0v[8], k1v[8];
    {
        const float bk0 = bk[j0], bk1 = bk[j0 + 1];
#pragma unroll
        for (int e = 0; e < 8; e++) {
            k0v[e] = warp_sum(pairsum(ak0[e])) + bk0;
            k1v[e] = warp_sum(pairsum(ak1[e])) + bk1;
        }
    }
    if (half == 0) {
        const float bq0 = bq[j0], bq1 = bq[j0 + 1];
#pragma unroll
        for (int b = 0; b < B_; b++) {
            float q0 = warp_sum(pairsum(aq0[b])) + bq0;
            float q1 = warp_sum(pairsum(aq1[b])) + bq1;
            if (lane == 0) { s_qv[pair][0][b] = q0; s_qv[pair][1][b] = q1; }
        }
    }
    __syncthreads();
    if (lane == 0) {
        const float inv_sqrt_h = rsqrtf((float)H_);
#pragma unroll
        for (int b = 0; b < B_; b++) {
            float q0 = s_qv[pair][0][b], q1 = s_qv[pair][1][b];
#pragma unroll
            for (int e = 0; e < 8; e++)
                s_attp[warp][b * 8 + e] = (q0 * k0v[e] + q1 * k1v[e]) * inv_sqrt_h;
        }
    }
    __syncthreads();
    if (tid < B_ * E_) {
        int b = tid >> 4, e = tid & 15, hf = e >> 3, el = e & 7;
        float s = 0.f;
#pragma unroll
        for (int pr = 0; pr < 4; pr++) s += s_attp[pr * 2 + hf][b * 8 + el];
        g_attp[blockIdx.x * (B_ * E_) + tid] = s;
    }
    __threadfence();
    __syncthreads();
    if (tid == 0) {
        int old = atomicAdd(&g_c3, 1);
        s_last = (old == NBLK_B - 1) ? 1 : 0;
    }
    __syncthreads();
    if (!s_last) return;

    // ================= epilogue (last block only, 256 threads) =================
    const int cur = *curp;
    {
        int o = tid & 63, qc = tid >> 6;   // 4 chunks of 64 blocks
        float s = 0.f;
#pragma unroll 8
        for (int c = 0; c < 64; c++) s += g_attp[(qc * 64 + c) * (B_ * E_) + o];
        s_red[qc][o] = s;
    }
    for (int h = tid; h < ED_; h += 256) {
        float a = 0.f;
#pragma unroll
        for (int i = 0; i < E_; i++) {
            int d = abs(i - cur);
            float rm = (float)avail[i] * ((i != cur) ? 1.f : 0.f) * (1.f / (float)max(d, 1));
            a += rm * edge[i * ED_ + h];
        }
        s_w[h] = a;
    }
    if (tid < E_) s_sb[tid] = spatial[abs(tid - cur)];
    __syncthreads();
    if (tid < B_ * E_)
        s_att[tid] = s_red[0][tid] + s_red[1][tid] + s_red[2][tid] + s_red[3][tid];

    for (int jj = 0; jj < 2; jj++) {
        int je = warp * 2 + jj;
        float s = 0.f;
#pragma unroll
        for (int t = 0; t < 16; t++)
            s += s_w[t * 32 + lane] * edge[je * ED_ + t * 32 + lane];
        s = warp_sum(s);
        if (lane == 0) s_eb[je] = s;
    }
    __syncthreads();

    if (warp == 0) {
        float av = (lane < E_) ? (float)avail[lane] : 0.f;
        float num_avail = warp_sum(av);
        float tprob = 1.f / num_avail;
        float logt = logf(tprob);
        float klacc = 0.f;
        int nidx = 0;
        for (int b = 0; b < B_; b++) {
            float sc = -1e30f;
            if (lane < E_) {
                bool ok = (avail[lane] > 0);
                sc = s_att[b * E_ + lane] + s_sb[lane] + s_eb[lane];
                sc = ok ? sc : -1e9f;
            }
            float m = sc;
#pragma unroll
            for (int o = 8; o > 0; o >>= 1) m = fmaxf(m, __shfl_xor_sync(0xffffffffu, m, o, 16));
            float ex = (lane < E_) ? __expf(sc - m) : 0.f;
            float sum = ex;
#pragma unroll
            for (int o = 8; o > 0; o >>= 1) sum += __shfl_xor_sync(0xffffffffu, sum, o, 16);
            float p = (lane < E_) ? (ex / sum) : 0.f;
            if (lane < E_) out[1 + b * E_ + lane] = p;
            float ps = fmaxf(p, 1e-10f);
            if (lane < E_) klacc += tprob * (logt - logf(ps));
            if (b == 0) {
                float pm = (lane < E_) ? p : -1.f;
                float mm = pm;
#pragma unroll
                for (int o = 16; o > 0; o >>= 1) mm = fmaxf(mm, __shfl_xor_sync(0xffffffffu, mm, o));
                unsigned bal = __ballot_sync(0xffffffffu, pm == mm);
                nidx = __ffs(bal) - 1;
            }
        }
        float kl = warp_sum(klacc);
        if (lane == 0) {
            out[0] = (kl / (float)B_) * 0.01f;
            out[1 + B_ * E_] = (float)nidx;
            g_c3 = 0;                     // reset for next graph replay
        }
    }
}

// ---------------- launch ----------------
extern "C" void kernel_launch(void* const* d_in, const int* in_sizes, int n_in,
                              void* d_out, int out_size) {
    const float* hid     = (const float*)d_in[0];
    const float* le      = (const float*)d_in[1];
    const float* ce      = (const float*)d_in[2];
    const float* spatial = (const float*)d_in[3];
    const float* edge    = (const float*)d_in[4];
    const float* gamma   = (const float*)d_in[5];
    const float* beta    = (const float*)d_in[6];
    const float* Wq      = (const float*)d_in[7];
    const float* bq      = (const float*)d_in[8];
    const float* Wk      = (const float*)d_in[9];
    const float* bk      = (const float*)d_in[10];
    // d_in[11], d_in[12] (Wv, bv) intentionally unused: v is dead in the reference
    const int*   curp    = (const int*)d_in[13];
    const int*   avail   = (const int*)d_in[14];
    float* out = (float*)d_out;

    kA<<<NBLK_A, 256>>>(hid, le, ce);
    kB0<<<64, 256>>>(le, gamma, beta, curp);
    kB<<<NBLK_B, 256>>>(Wq, bq, Wk, bk, spatial, edge, curp, avail, out);
}